// round 3
// baseline (speedup 1.0000x reference)
#include <cuda_runtime.h>
#include <math.h>

#define TRAJ_NUM 8
#define EVAL     30
#define PTS      (TRAJ_NUM*EVAL)   // 240 points per group
#define SGM_T    2.0f
#define D0c      0.5f
#define Rc       0.3f
#define VOX      0.2f
#define INV_VOX  5.0f

#define MAXG 1024

// scratch (no allocations allowed)
__device__ int g_mn0[MAXG*3];
__device__ int g_mx0[MAXG*3];

// replay-safe grid barrier state
__device__ unsigned int g_count = 0;
__device__ volatile unsigned int g_gen = 0;

__device__ __forceinline__ float warpMinF(float v) {
    #pragma unroll
    for (int o = 16; o > 0; o >>= 1) v = fminf(v, __shfl_xor_sync(0xffffffff, v, o));
    return v;
}
__device__ __forceinline__ float warpMaxF(float v) {
    #pragma unroll
    for (int o = 16; o > 0; o >>= 1) v = fmaxf(v, __shfl_xor_sync(0xffffffff, v, o));
    return v;
}
__device__ __forceinline__ int warpMaxI(int v) {
    #pragma unroll
    for (int o = 16; o > 0; o >>= 1) v = max(v, __shfl_xor_sync(0xffffffff, v, o));
    return v;
}

__global__ void __launch_bounds__(512, 2)
fused_kernel(const float* __restrict__ Df, const float* __restrict__ Dp,
             const float* __restrict__ L,  const float* __restrict__ sdf,
             const float* __restrict__ min_bounds,
             const float* __restrict__ sdf_shapes,
             const int* __restrict__ map_id,
             float* __restrict__ out, int G)
{
    const int g    = blockIdx.x;
    const int t    = threadIdx.x;
    const int wid  = t >> 5;            // 0..15
    const int lane = t & 31;
    const int half = t >> 8;            // 0 or 1
    const int idx  = t & 255;           // point index within group

    __shared__ float Ls[36];
    __shared__ float s_pos[PTS][3];
    __shared__ float wmin[16][3], wmax[16][3];
    __shared__ int   wredA[16][3], wredB[16][3];
    __shared__ int   s_maxspan[3], s_shift[3];
    __shared__ float s_part[2][PTS];
    __shared__ float cs[PTS];

    if (t < 36) Ls[t] = L[t];
    __syncthreads();

    // ---------------- Phase 1: positions (lower half) + group AABB --------
    const bool pact = (t < PTS);          // position-computing threads
    float p[3] = {0.f, 0.f, 0.f};
    if (pact) {
        int traj = t / EVAL;
        int n    = t % EVAL;
        int b    = g * TRAJ_NUM + traj;

        float start = SGM_T / (float)EVAL;
        float step  = (SGM_T - start) / (float)(EVAL - 1);
        float tn    = start + (float)n * step;

        float tp[6];
        tp[0] = 1.f;
        #pragma unroll
        for (int k = 1; k < 6; k++) tp[k] = tp[k-1] * tn;

        #pragma unroll
        for (int i = 0; i < 3; i++) {
            float d[6];
            d[0] = Df[b*9 + i*3 + 0];
            d[1] = Df[b*9 + i*3 + 1];
            d[2] = Df[b*9 + i*3 + 2];
            d[3] = Dp[b*9 + i*3 + 0];
            d[4] = Dp[b*9 + i*3 + 1];
            d[5] = Dp[b*9 + i*3 + 2];
            float s = 0.f;
            #pragma unroll
            for (int j = 0; j < 6; j++) {
                float c = 0.f;
                #pragma unroll
                for (int k = 0; k < 6; k++) c += Ls[j*6 + k] * d[k];
                s += tp[j] * c;
            }
            p[i] = s;
            s_pos[t][i] = s;
        }
    }

    const int mid = map_id[g];
    float mb[3];
    #pragma unroll
    for (int i = 0; i < 3; i++) mb[i] = min_bounds[mid*3 + i];

    #pragma unroll
    for (int i = 0; i < 3; i++) {
        float vmin = pact ? p[i] :  3.4e38f;
        float vmax = pact ? p[i] : -3.4e38f;
        vmin = warpMinF(vmin);
        vmax = warpMaxF(vmax);
        if (lane == 0) { wmin[wid][i] = vmin; wmax[wid][i] = vmax; }
    }
    __syncthreads();
    if (t < 3) {
        float vmin =  3.4e38f, vmax = -3.4e38f;
        #pragma unroll
        for (int w = 0; w < 16; w++) {
            vmin = fminf(vmin, wmin[w][t]);
            vmax = fmaxf(vmax, wmax[w][t]);
        }
        g_mn0[g*3 + t] = (int)truncf((vmin - mb[t]) * INV_VOX);
        g_mx0[g*3 + t] = (int)truncf((vmax - mb[t]) * INV_VOX);
    }
    __syncthreads();

    // ---------------- grid barrier (replay-safe) ---------------------------
    if (t == 0) {
        __threadfence();
        unsigned int gen = g_gen;
        if (atomicAdd(&g_count, 1) == gridDim.x - 1) {
            g_count = 0;
            __threadfence();
            g_gen = gen + 1;
        } else {
            while (g_gen == gen) { }
        }
        __threadfence();
    }
    __syncthreads();

    // ---------------- Phase 2: redundant cross-group box logic -------------
    int span[3] = {0, 0, 0};
    int tm0[3]  = {0, 0, 0}, tx0[3] = {0, 0, 0}, tshp[3] = {1, 1, 1};
    const bool gact = (t < G);            // t handles group t (G=256)
    if (gact) {
        int tmid = map_id[t];
        #pragma unroll
        for (int i = 0; i < 3; i++) {
            tm0[i]  = g_mn0[t*3 + i];
            tx0[i]  = g_mx0[t*3 + i];
            tshp[i] = (int)sdf_shapes[tmid*3 + i];
            span[i] = tx0[i] - tm0[i];
        }
    }
    #pragma unroll
    for (int i = 0; i < 3; i++) {
        int v = warpMaxI(span[i]);        // inactive lanes contribute 0 (span>=0)
        if (lane == 0) wredA[wid][i] = v;
    }
    __syncthreads();
    if (t < 3) {
        int v = 0;
        #pragma unroll
        for (int w = 0; w < 16; w++) v = max(v, wredA[w][t]);
        s_maxspan[t] = v;
    }
    __syncthreads();

    int sc[3] = {0, 0, 0};
    if (gact) {
        #pragma unroll
        for (int i = 0; i < 3; i++) {
            int c  = (tm0[i] + tx0[i]) >> 1;
            int ms = s_maxspan[i];
            int mnl = c - (ms >> 1) - 5;
            int mxl = c + (ms >> 1) + 5;
            int nmn = max(mnl, 0);
            mxl += nmn - mnl; mnl = nmn;
            int nmx = min(mxl, tshp[i]);
            mnl -= mxl - nmx;
            sc[i] = max(-min(mnl, 0), 0);
        }
    }
    #pragma unroll
    for (int i = 0; i < 3; i++) {
        int v = warpMaxI(sc[i]);          // inactive contribute 0 (sc>=0)
        if (lane == 0) wredB[wid][i] = v;
    }
    __syncthreads();
    if (t < 3) {
        int v = 0;
        #pragma unroll
        for (int w = 0; w < 16; w++) v = max(v, wredB[w][t]);
        s_shift[t] = v;
    }
    __syncthreads();

    // own group's final box (all threads compute identically)
    int mn[3], ls[3], shp[3];
    #pragma unroll
    for (int i = 0; i < 3; i++) {
        int m0 = g_mn0[g*3 + i];
        int x0 = g_mx0[g*3 + i];
        shp[i] = (int)sdf_shapes[mid*3 + i];
        int c  = (m0 + x0) >> 1;
        int ms = s_maxspan[i];
        int m  = c - (ms >> 1) - 5;
        int x  = c + (ms >> 1) + 5;
        int nm = max(m, 0);
        x += nm - m; m = nm;
        int nx = min(x, shp[i]);
        m -= x - nx; x = nx;
        m += s_shift[i];
        mn[i] = m;
        ls[i] = x - m;
    }

    // ---------------- Phase 3: trilinear sample, 2 threads per point -------
    const int Wm = shp[0], Hm = shp[1], Dm = shp[2];
    const long base = (long)mid * Dm * Hm * Wm;
    const bool act = (idx < PTS);

    if (act) {
        float gx = (s_pos[idx][0] - ((float)mn[0] * VOX + mb[0])) * INV_VOX;
        float gy = (s_pos[idx][1] - ((float)mn[1] * VOX + mb[1])) * INV_VOX;
        float gz = (s_pos[idx][2] - ((float)mn[2] * VOX + mb[2])) * INV_VOX;

        float fx0 = floorf(gx), fy0 = floorf(gy), fz0 = floorf(gz);
        int l0x = (int)fx0, l0y = (int)fy0, l0z = (int)fz0;
        float f0 = gx - fx0, f1 = gy - fy0, f2 = gz - fz0;

        float wx[2] = {1.f - f0, f0};
        float wy[2] = {1.f - f1, f1};
        float wzh   = half ? f2 : (1.f - f2);

        // this thread's z-plane corner
        int ilz = l0z + half;
        bool zin = (ilz >= 0) && (ilz < ls[2]);
        int igz  = min(max(ilz + mn[2], 0), Dm - 1);

        float part = 0.f;
        #pragma unroll
        for (int dx = 0; dx < 2; dx++)
        #pragma unroll
        for (int dy = 0; dy < 2; dy++) {
            int ilx = l0x + dx, ily = l0y + dy;
            bool inb = zin && (ilx >= 0) && (ilx < ls[0]) &&
                       (ily >= 0) && (ily < ls[1]);
            int igx = min(max(ilx + mn[0], 0), Wm - 1);
            int igy = min(max(ily + mn[1], 0), Hm - 1);
            float val = __ldg(&sdf[base + ((long)igz * Hm + igy) * Wm + igx]);
            float w = wx[dx] * wy[dy] * wzh;
            part += inb ? w * val : 0.f;
        }
        s_part[half][idx] = part;
    }
    __syncthreads();

    if (act && half == 0) {
        float gx = (s_pos[idx][0] - ((float)mn[0] * VOX + mb[0])) * INV_VOX;
        float gy = (s_pos[idx][1] - ((float)mn[1] * VOX + mb[1])) * INV_VOX;
        float gz = (s_pos[idx][2] - ((float)mn[2] * VOX + mb[2])) * INV_VOX;
        float gpx = 2.f * gx / (float)(ls[0] - 1) - 1.f;
        float gpy = 2.f * gy / (float)(ls[1] - 1) - 1.f;
        float gpz = 2.f * gz / (float)(ls[2] - 1) - 1.f;
        bool valid = (gpx <  0.99f) && (gpx > -0.99f) &&
                     (gpy <  0.99f) && (gpy > -0.99f) &&
                     (gpz <  0.99f) && (gpz > -0.99f);

        float acc = s_part[0][idx] + s_part[1][idx];
        cs[idx] = valid ? __expf(-(acc - D0c) / Rc) : 0.f;
    }
    __syncthreads();

    if (t < TRAJ_NUM) {
        const float dt = SGM_T / (float)EVAL;
        float s = 0.f;
        #pragma unroll
        for (int k = 0; k < EVAL; k++) s += cs[t*EVAL + k];
        out[g*TRAJ_NUM + t] = s * dt;
    }
}

// ---------------------------------------------------------------------------
extern "C" void kernel_launch(void* const* d_in, const int* in_sizes, int n_in,
                              void* d_out, int out_size)
{
    const float* Df         = (const float*)d_in[0];
    const float* Dp         = (const float*)d_in[1];
    const float* L          = (const float*)d_in[2];
    const float* sdf_maps   = (const float*)d_in[3];
    const float* min_bounds = (const float*)d_in[4];
    const float* sdf_shapes = (const float*)d_in[5];
    const int*   map_id     = (const int*)d_in[6];

    int G = in_sizes[6];

    fused_kernel<<<G, 512>>>(Df, Dp, L, sdf_maps, min_bounds, sdf_shapes,
                             map_id, (float*)d_out, G);
}